// round 12
// baseline (speedup 1.0000x reference)
#include <cuda_runtime.h>
#include <cstdint>

#define ML 6
#define NN 4096
#define DD 512
#define NPAIR 21

// ---------------------------------------------------------------------------
// Scratch (__device__ globals only)
// ---------------------------------------------------------------------------
__device__ float  g_Yhi[ML * DD * NN]; // tf32(y), transposed [m][d][n]
__device__ float  g_Ylo[ML * DD * NN]; // tf32(y - hi), transposed
__device__ float  g_mu[ML * DD];
__device__ float  g_rd[ML * NN];       // ||x_n||^2 (fp32)
__device__ float  g_rq[ML * NN];       // ||hi_n + lo_n||^2 (fp32)
__device__ double g_F[NPAIR];
__device__ double g_T[36];
__device__ double g_P[36];
__device__ double g_s[ML];

__device__ __forceinline__ uint32_t smem_u32(const void* p) {
    uint32_t a;
    asm("{ .reg .u64 t; cvta.to.shared.u64 t, %1; cvt.u32.u64 %0, t; }" : "=r"(a) : "l"(p));
    return a;
}
__device__ __forceinline__ void cp16(uint32_t dst, const void* src) {
    asm volatile("cp.async.cg.shared.global [%0], [%1], 16;" :: "r"(dst), "l"(src));
}
__device__ __forceinline__ float tf32_round(float v) {
    uint32_t u;
    asm("cvt.rna.tf32.f32 %0, %1;" : "=r"(u) : "f"(v));
    return __uint_as_float(u);
}
__device__ __forceinline__ void ldsm4(uint32_t& r0, uint32_t& r1, uint32_t& r2,
                                      uint32_t& r3, uint32_t addr) {
    asm volatile("ldmatrix.sync.aligned.m8n8.x4.shared.b16 {%0,%1,%2,%3}, [%4];"
                 : "=r"(r0), "=r"(r1), "=r"(r2), "=r"(r3) : "r"(addr));
}
__device__ __forceinline__ void mma_tf32(float* c, const uint32_t* a, const uint32_t* b) {
    asm volatile("mma.sync.aligned.m16n8k8.row.col.f32.tf32.tf32.f32 "
                 "{%0,%1,%2,%3}, {%4,%5,%6,%7}, {%8,%9}, {%0,%1,%2,%3};"
                 : "+f"(c[0]), "+f"(c[1]), "+f"(c[2]), "+f"(c[3])
                 : "r"(a[0]), "r"(a[1]), "r"(a[2]), "r"(a[3]), "r"(b[0]), "r"(b[1]));
}

// ---------------------------------------------------------------------------
// Kernel 1: column means; zero F accumulators.
// ---------------------------------------------------------------------------
__global__ void k_mean(const float* __restrict__ X) {
    int m = blockIdx.x, c0 = blockIdx.y * 32;
    int tx = threadIdx.x, ty = threadIdx.y;
    if (blockIdx.x == 0 && blockIdx.y == 0 && ty == 0 && tx < NPAIR) g_F[tx] = 0.0;
    const float* base = X + (size_t)m * NN * DD + c0 + tx;
    float s = 0.f;
    for (int n = ty; n < NN; n += 8) s += base[(size_t)n * DD];
    __shared__ float sh[8][33];
    sh[ty][tx] = s;
    __syncthreads();
    if (ty == 0) {
        float t = 0.f;
#pragma unroll
        for (int r = 0; r < 8; r++) t += sh[r][tx];
        g_mu[m * DD + c0 + tx] = t * (1.f / NN);
    }
}

// ---------------------------------------------------------------------------
// Kernel 2: center rows, split into tf32 hi/lo, write both transposed.
// ---------------------------------------------------------------------------
__global__ void k_center_t(const float* __restrict__ X) {
    extern __shared__ float cs[];
    float* th = cs;                                // [32][513] hi
    float* tl = cs + 32 * 513;                     // [32][513] lo
    float4* smu = (float4*)(cs + 2 * 32 * 513);    // [128]

    int blk = blockIdx.x;
    int m = blk >> 7;
    int n0 = (blk & 127) * 32;
    int tid = threadIdx.x, warp = tid >> 5, lane = tid & 31;

    if (tid < DD / 4) smu[tid] = ((const float4*)(g_mu + m * DD))[tid];
    __syncthreads();

#pragma unroll
    for (int rr = 0; rr < 4; rr++) {
        int nloc = warp * 4 + rr;
        int row = m * NN + n0 + nloc;
        const float4* xr = (const float4*)(X + (size_t)row * DD);
        float sx = 0.f, sy = 0.f;
#pragma unroll
        for (int jj = 0; jj < 4; jj++) {
            int idx = lane + 32 * jj;
            float4 x = xr[idx];
            float4 mu = smu[idx];
            float y[4] = {x.x - mu.x, x.y - mu.y, x.z - mu.z, x.w - mu.w};
            float* hp = &th[nloc * 513 + idx * 4];
            float* lp = &tl[nloc * 513 + idx * 4];
#pragma unroll
            for (int v = 0; v < 4; v++) {
                float hi = tf32_round(y[v]);
                float lo = tf32_round(y[v] - hi);
                hp[v] = hi; lp[v] = lo;
                float ye = hi + lo;
                sy += ye * ye;
            }
            sx += x.x * x.x + x.y * x.y + x.z * x.z + x.w * x.w;
        }
#pragma unroll
        for (int o = 16; o; o >>= 1) {
            sx += __shfl_xor_sync(0xffffffffu, sx, o);
            sy += __shfl_xor_sync(0xffffffffu, sy, o);
        }
        if (lane == 0) { g_rd[row] = sx; g_rq[row] = sy; }
    }
    __syncthreads();

    float* yh = g_Yhi + (size_t)m * DD * NN + n0;
    float* yl = g_Ylo + (size_t)m * DD * NN + n0;
#pragma unroll 8
    for (int d = warp; d < DD; d += 8) {
        yh[(size_t)d * NN + lane] = th[lane * 513 + d];
        yl[(size_t)d * NN + lane] = tl[lane * 513 + d];
    }
}

// ---------------------------------------------------------------------------
// Kernel 3 (hot): 3xTF32 mma.sync GEMM, full K=4096 per CTA, tile 128x64.
// 600 active CTAs of ~196Kcyc — halves wave quantization vs 128x128 (R9)
// with NO scratch materialization (F = ||C||^2 stays exact per tile).
// Diagonal pairs: per-element symmetry weights in the epilogue.
// Warp tile 64x16 (wm 0..1, wn 0..3), KC=32, 3-stage cp.async. grid(4,8,21).
// ---------------------------------------------------------------------------
#define KC 32
#define NSTG 3
#define SUBA (128 * KC * 4)                 // 16 KB
#define SUBB (64 * KC * 4)                  // 8 KB
#define STG_BYTES (2 * SUBA + 2 * SUBB)     // Ahi|Alo|Bhi|Blo = 48 KB
#define GEMM_SMEM (NSTG * STG_BYTES)        // 147456

__global__ void __launch_bounds__(256, 1) k_gemm_mma() {
    extern __shared__ char smem[];
    uint32_t sb = smem_u32(smem);
    int tid = threadIdx.x, wid = tid >> 5, lane = tid & 31;

    int p = blockIdx.z;
    int i = 0, pp = p;
    while (pp >= ML - i) { pp -= ML - i; i++; }
    int j = i + pp;

    int bx = blockIdx.x, by = blockIdx.y;
    bool diag = (i == j);
    if (diag && by < 2 * bx) return;              // tile entirely below diagonal
    bool straddle = diag && (by < 2 * bx + 2);    // needs per-element weights
    double wscale = (diag && !straddle) ? 2.0 : 1.0;

    size_t offA = ((size_t)i * DD + bx * 128) * NN;
    size_t offB = ((size_t)j * DD + by * 64) * NN;
    const float* Ah = g_Yhi + offA;
    const float* Al = g_Ylo + offA;
    const float* Bh = g_Yhi + offB;
    const float* Bl = g_Ylo + offB;
    const int NCH = NN / KC;  // 128 chunks

    int wm = wid & 1, wn = wid >> 1;   // warp: 64 rows x 16 cols

    int a_row_off = lane & 15;
    int a_kh = lane >> 4;
    int b_row_off = (lane & 7) + ((lane >> 4) & 1) * 8;
    int b_kh = (lane >> 3) & 1;

    uint32_t arow[4], aph[4];
#pragma unroll
    for (int mt = 0; mt < 4; mt++) {
        int r = wm * 64 + mt * 16 + a_row_off;
        arow[mt] = r * 128; aph[mt] = r & 7;
    }
    uint32_t brow, bph;
    {
        int r = wn * 16 + b_row_off;
        brow = r * 128; bph = r & 7;
    }

    float c[4][2][4];    // short-chain mma accumulator (reset per chunk)
    float tot[4][2][4];  // unbiased fp32 running total (FADD, RNE)
#pragma unroll
    for (int mt = 0; mt < 4; mt++)
#pragma unroll
        for (int nt = 0; nt < 2; nt++)
#pragma unroll
            for (int v = 0; v < 4; v++) { c[mt][nt][v] = 0.f; tot[mt][nt][v] = 0.f; }

    auto load_stage = [&](int st, int kb) {
        uint32_t s0 = sb + st * STG_BYTES;
        // A hi/lo: 128 rows x 8 float4 = 1024 -> 4 per thread
#pragma unroll
        for (int t = 0; t < 4; t++) {
            int o = tid + t * 256;
            int r = o >> 3, g = o & 7;
            uint32_t sw = r * 128 + ((g ^ (r & 7)) * 16);
            cp16(s0 + sw, Ah + (size_t)r * NN + kb + g * 4);
            cp16(s0 + SUBA + sw, Al + (size_t)r * NN + kb + g * 4);
        }
        // B hi/lo: 64 rows x 8 float4 = 512 -> 2 per thread
#pragma unroll
        for (int t = 0; t < 2; t++) {
            int o = tid + t * 256;
            int r = o >> 3, g = o & 7;
            uint32_t sw = r * 128 + ((g ^ (r & 7)) * 16);
            cp16(s0 + 2 * SUBA + sw, Bh + (size_t)r * NN + kb + g * 4);
            cp16(s0 + 2 * SUBA + SUBB + sw, Bl + (size_t)r * NN + kb + g * 4);
        }
    };

    load_stage(0, 0);
    asm volatile("cp.async.commit_group;");
    load_stage(1, KC);
    asm volatile("cp.async.commit_group;");

    for (int ch = 0; ch < NCH; ch++) {
        asm volatile("cp.async.wait_group %0;" :: "n"(1));
        __syncthreads();

        if (ch + 2 < NCH) load_stage((ch + 2) % NSTG, (ch + 2) * KC);
        asm volatile("cp.async.commit_group;");

        uint32_t s0 = sb + (ch % NSTG) * STG_BYTES;
        uint32_t sAh = s0, sAl = s0 + SUBA;
        uint32_t sBh = s0 + 2 * SUBA, sBl = s0 + 2 * SUBA + SUBB;

#pragma unroll
        for (int ks = 0; ks < 4; ks++) {
            uint32_t ah[4][4], al[4][4];
#pragma unroll
            for (int mt = 0; mt < 4; mt++) {
                uint32_t g = (uint32_t)(ks * 2 + a_kh) ^ aph[mt];
                ldsm4(ah[mt][0], ah[mt][1], ah[mt][2], ah[mt][3], sAh + arow[mt] + g * 16);
                ldsm4(al[mt][0], al[mt][1], al[mt][2], al[mt][3], sAl + arow[mt] + g * 16);
            }
            uint32_t bh[2][2], bl[2][2];
            {
                uint32_t g = (uint32_t)(ks * 2 + b_kh) ^ bph;
                ldsm4(bh[0][0], bh[0][1], bh[1][0], bh[1][1], sBh + brow + g * 16);
                ldsm4(bl[0][0], bl[0][1], bl[1][0], bl[1][1], sBl + brow + g * 16);
            }
            // independent MMA passes (no back-to-back RAW on same accumulator)
#pragma unroll
            for (int mt = 0; mt < 4; mt++)
#pragma unroll
                for (int nt = 0; nt < 2; nt++)
                    mma_tf32(c[mt][nt], ah[mt], bh[nt]);   // hi*hi
#pragma unroll
            for (int mt = 0; mt < 4; mt++)
#pragma unroll
                for (int nt = 0; nt < 2; nt++)
                    mma_tf32(c[mt][nt], ah[mt], bl[nt]);   // hi*lo
#pragma unroll
            for (int mt = 0; mt < 4; mt++)
#pragma unroll
                for (int nt = 0; nt < 2; nt++)
                    mma_tf32(c[mt][nt], al[mt], bh[nt]);   // lo*hi
        }

        // flush short RZ chain into unbiased fp32 total; reset (bias fix)
#pragma unroll
        for (int mt = 0; mt < 4; mt++)
#pragma unroll
            for (int nt = 0; nt < 2; nt++)
#pragma unroll
                for (int v = 0; v < 4; v++) {
                    tot[mt][nt][v] += c[mt][nt][v];
                    c[mt][nt][v] = 0.f;
                }
    }

    // epilogue: Frobenius square-sum (double) with symmetry weights
    double s = 0.0;
    if (!straddle) {
#pragma unroll
        for (int mt = 0; mt < 4; mt++)
#pragma unroll
            for (int nt = 0; nt < 2; nt++)
#pragma unroll
                for (int v = 0; v < 4; v++) {
                    double f = (double)tot[mt][nt][v];
                    s += f * f;
                }
        s *= wscale;
    } else {
        // per-element: weight 2 above diagonal, 1 on, 0 below
        int r0 = bx * 128 + wm * 64 + (lane >> 2);
        int c0g = by * 64 + wn * 16 + (lane & 3) * 2;
#pragma unroll
        for (int mt = 0; mt < 4; mt++)
#pragma unroll
            for (int nt = 0; nt < 2; nt++)
#pragma unroll
                for (int v = 0; v < 4; v++) {
                    int row = r0 + mt * 16 + ((v >> 1) << 3);
                    int col = c0g + nt * 8 + (v & 1);
                    double wv = (col > row) ? 2.0 : (col == row ? 1.0 : 0.0);
                    double f = (double)tot[mt][nt][v];
                    s += wv * f * f;
                }
    }
#pragma unroll
    for (int o = 16; o; o >>= 1) s += __shfl_xor_sync(0xffffffffu, s, o);
    __shared__ double red[8];
    if (lane == 0) red[wid] = s;
    __syncthreads();
    if (tid < 8) {
        double v = red[tid];
#pragma unroll
        for (int o = 4; o; o >>= 1) v += __shfl_xor_sync(0xffu, v, o);
        if (tid == 0) atomicAdd(&g_F[p], v);
    }
}

// ---------------------------------------------------------------------------
// Kernel 4: scalar correction sums (double).
// ---------------------------------------------------------------------------
__global__ void k_small() {
    int i = blockIdx.x / 6, j = blockIdx.x % 6;
    const float* qi = g_rq + i * NN;
    const float* dj = g_rd + j * NN;
    const float* di = g_rd + i * NN;
    double aqd = 0.0, add = 0.0, as = 0.0;
    for (int n = threadIdx.x; n < NN; n += 256) {
        double dv = (double)dj[n];
        aqd += (double)qi[n] * dv;
        add += (double)di[n] * dv;
        as += dv;
    }
    int lane = threadIdx.x & 31;
#pragma unroll
    for (int o = 16; o; o >>= 1) {
        aqd += __shfl_xor_sync(0xffffffffu, aqd, o);
        add += __shfl_xor_sync(0xffffffffu, add, o);
        as  += __shfl_xor_sync(0xffffffffu, as, o);
    }
    __shared__ double r0[8], r1[8], r2[8];
    if (lane == 0) { int w = threadIdx.x >> 5; r0[w] = aqd; r1[w] = add; r2[w] = as; }
    __syncthreads();
    if (threadIdx.x == 0) {
        double t0 = 0, t1 = 0, t2 = 0;
#pragma unroll
        for (int w = 0; w < 8; w++) { t0 += r0[w]; t1 += r1[w]; t2 += r2[w]; }
        g_T[i * 6 + j] = t0;
        g_P[i * 6 + j] = t1;
        if (i == j) g_s[i] = t2;
    }
}

// ---------------------------------------------------------------------------
// Kernel 5: finalize.
// ---------------------------------------------------------------------------
__global__ void k_final(float* __restrict__ out) {
    __shared__ double S[36];
    int t = threadIdx.x;
    if (t < 36) {
        int i = t / 6, j = t % 6;
        int a = i < j ? i : j, b = i < j ? j : i;
        int p = a * ML - a * (a + 1) / 2 + b;
        double hs = g_F[p] - g_T[i * 6 + j] - g_T[j * 6 + i]
                  + (1.0 - 2.0 / (double)NN) * g_P[i * 6 + j]
                  + g_s[i] * g_s[j] / ((double)NN * (double)NN);
        S[t] = fabs(hs);
    }
    __syncthreads();
    if (t < 36) {
        int i = t / 6, j = t % 6;
        double v = (i == j) ? 1.0 : S[i * 6 + j] / sqrt(S[i * 6 + i] * S[j * 6 + j] + 1e-6);
        out[t] = (float)v;
    }
    if (t == 0) {
        double l = 0.0;
        for (int i = 0; i < 6; i++)
            for (int j = 0; j < i; j++)
                l += S[i * 6 + j] / sqrt(S[i * 6 + i] * S[j * 6 + j] + 1e-6);
        out[36] = (float)l;
    }
}

// ---------------------------------------------------------------------------
extern "C" void kernel_launch(void* const* d_in, const int* in_sizes, int n_in,
                              void* d_out, int out_size) {
    const float* X = (const float*)d_in[0];
    float* out = (float*)d_out;
    (void)in_sizes; (void)n_in; (void)out_size;

    cudaFuncSetAttribute(k_gemm_mma, cudaFuncAttributeMaxDynamicSharedMemorySize, GEMM_SMEM);
    cudaFuncSetAttribute(k_center_t, cudaFuncAttributeMaxDynamicSharedMemorySize,
                         (2 * 32 * 513 + 512) * 4);

    dim3 g1(ML, DD / 32), b1(32, 8);
    k_mean<<<g1, b1>>>(X);
    k_center_t<<<ML * NN / 32, 256, (2 * 32 * 513 + 512) * 4>>>(X);
    dim3 g3(4, 8, NPAIR);
    k_gemm_mma<<<g3, 256, GEMM_SMEM>>>();
    k_small<<<36, 256>>>();
    k_final<<<1, 64>>>(out);
}

// round 13
// speedup vs baseline: 2.9910x; 2.9910x over previous
#include <cuda_runtime.h>
#include <cuda_bf16.h>
#include <cstdint>

#define ML 6
#define NN 4096
#define DD 512
#define NPAIR 21

// ---------------------------------------------------------------------------
// Scratch (__device__ globals only)
// ---------------------------------------------------------------------------
__device__ __nv_bfloat16 g_Yhi[ML * DD * NN]; // bf16(y), transposed [m][d][n]
__device__ __nv_bfloat16 g_Ylo[ML * DD * NN]; // bf16(y - hi), transposed
__device__ float  g_mu[ML * DD];
__device__ float  g_rd[ML * NN];       // ||x_n||^2 (fp32)
__device__ float  g_rq[ML * NN];       // ||hi_n + lo_n||^2 (fp32)
__device__ double g_F[NPAIR];
__device__ double g_T[36];
__device__ double g_P[36];
__device__ double g_s[ML];

__device__ __forceinline__ uint32_t smem_u32(const void* p) {
    uint32_t a;
    asm("{ .reg .u64 t; cvta.to.shared.u64 t, %1; cvt.u32.u64 %0, t; }" : "=r"(a) : "l"(p));
    return a;
}
__device__ __forceinline__ void cp16(uint32_t dst, const void* src) {
    asm volatile("cp.async.cg.shared.global [%0], [%1], 16;" :: "r"(dst), "l"(src));
}
__device__ __forceinline__ void ldsm4(uint32_t& r0, uint32_t& r1, uint32_t& r2,
                                      uint32_t& r3, uint32_t addr) {
    asm volatile("ldmatrix.sync.aligned.m8n8.x4.shared.b16 {%0,%1,%2,%3}, [%4];"
                 : "=r"(r0), "=r"(r1), "=r"(r2), "=r"(r3) : "r"(addr));
}
__device__ __forceinline__ void mma_bf16(float* c, const uint32_t* a, const uint32_t* b) {
    asm volatile("mma.sync.aligned.m16n8k16.row.col.f32.bf16.bf16.f32 "
                 "{%0,%1,%2,%3}, {%4,%5,%6,%7}, {%8,%9}, {%0,%1,%2,%3};"
                 : "+f"(c[0]), "+f"(c[1]), "+f"(c[2]), "+f"(c[3])
                 : "r"(a[0]), "r"(a[1]), "r"(a[2]), "r"(a[3]), "r"(b[0]), "r"(b[1]));
}

// ---------------------------------------------------------------------------
// Kernel 1: column means; zero F accumulators.
// ---------------------------------------------------------------------------
__global__ void k_mean(const float* __restrict__ X) {
    int m = blockIdx.x, c0 = blockIdx.y * 32;
    int tx = threadIdx.x, ty = threadIdx.y;
    if (blockIdx.x == 0 && blockIdx.y == 0 && ty == 0 && tx < NPAIR) g_F[tx] = 0.0;
    const float* base = X + (size_t)m * NN * DD + c0 + tx;
    float s = 0.f;
    for (int n = ty; n < NN; n += 8) s += base[(size_t)n * DD];
    __shared__ float sh[8][33];
    sh[ty][tx] = s;
    __syncthreads();
    if (ty == 0) {
        float t = 0.f;
#pragma unroll
        for (int r = 0; r < 8; r++) t += sh[r][tx];
        g_mu[m * DD + c0 + tx] = t * (1.f / NN);
    }
}

// ---------------------------------------------------------------------------
// Kernel 2: center rows, split into bf16 hi/lo, write both transposed (bf16).
// q computed from (hi+lo) so corrections match the GEMM's effective data.
// ---------------------------------------------------------------------------
__global__ void k_center_t(const float* __restrict__ X) {
    extern __shared__ float cs[];
    float* th = cs;                                // [32][513] hi (bf16 values)
    float* tl = cs + 32 * 513;                     // [32][513] lo (bf16 values)
    float4* smu = (float4*)(cs + 2 * 32 * 513);    // [128]

    int blk = blockIdx.x;
    int m = blk >> 7;
    int n0 = (blk & 127) * 32;
    int tid = threadIdx.x, warp = tid >> 5, lane = tid & 31;

    if (tid < DD / 4) smu[tid] = ((const float4*)(g_mu + m * DD))[tid];
    __syncthreads();

#pragma unroll
    for (int rr = 0; rr < 4; rr++) {
        int nloc = warp * 4 + rr;
        int row = m * NN + n0 + nloc;
        const float4* xr = (const float4*)(X + (size_t)row * DD);
        float sx = 0.f, sy = 0.f;
#pragma unroll
        for (int jj = 0; jj < 4; jj++) {
            int idx = lane + 32 * jj;
            float4 x = xr[idx];
            float4 mu = smu[idx];
            float y[4] = {x.x - mu.x, x.y - mu.y, x.z - mu.z, x.w - mu.w};
            float* hp = &th[nloc * 513 + idx * 4];
            float* lp = &tl[nloc * 513 + idx * 4];
#pragma unroll
            for (int v = 0; v < 4; v++) {
                float hi = __bfloat162float(__float2bfloat16(y[v]));
                float lo = __bfloat162float(__float2bfloat16(y[v] - hi));
                hp[v] = hi; lp[v] = lo;
                float ye = hi + lo;
                sy += ye * ye;
            }
            sx += x.x * x.x + x.y * x.y + x.z * x.z + x.w * x.w;
        }
#pragma unroll
        for (int o = 16; o; o >>= 1) {
            sx += __shfl_xor_sync(0xffffffffu, sx, o);
            sy += __shfl_xor_sync(0xffffffffu, sy, o);
        }
        if (lane == 0) { g_rd[row] = sx; g_rq[row] = sy; }
    }
    __syncthreads();

    __nv_bfloat16* yh = g_Yhi + (size_t)m * DD * NN + n0;
    __nv_bfloat16* yl = g_Ylo + (size_t)m * DD * NN + n0;
#pragma unroll 8
    for (int d = warp; d < DD; d += 8) {
        yh[(size_t)d * NN + lane] = __float2bfloat16(th[lane * 513 + d]);  // exact
        yl[(size_t)d * NN + lane] = __float2bfloat16(tl[lane * 513 + d]);  // exact
    }
}

// ---------------------------------------------------------------------------
// Kernel 3 (hot): 3xBF16 m16n8k16 mma.sync GEMM, full K=4096 per CTA.
// C = hi.hi + hi.lo + lo.hi (lo.lo ~2^-18 dropped). Same smem geometry,
// swizzle and flush cadence (12-mma chains) as the proven R9 tf32 kernel;
// bf16 doubles MACs/instr. Tile 128x128, warp 64x32, KC=64 (128B rows),
// 3-stage cp.async. grid(4,4,21), diag tiles skipped below diagonal.
// ---------------------------------------------------------------------------
#define KC 64
#define NSTG 3
#define SUB (128 * KC * 2)                  // 16 KB per sub-tile (bf16)
#define STG_BYTES (4 * SUB)                 // Ahi|Alo|Bhi|Blo = 64 KB
#define GEMM_SMEM (NSTG * STG_BYTES)        // 196608

__global__ void __launch_bounds__(256, 1) k_gemm_mma() {
    extern __shared__ char smem[];
    uint32_t sb = smem_u32(smem);
    int tid = threadIdx.x, wid = tid >> 5, lane = tid & 31;

    int p = blockIdx.z;
    int i = 0, pp = p;
    while (pp >= ML - i) { pp -= ML - i; i++; }
    int j = i + pp;

    bool diag = (i == j);
    if (diag && blockIdx.x > blockIdx.y) return;
    double wgt = (diag && blockIdx.x < blockIdx.y) ? 2.0 : 1.0;

    size_t offA = ((size_t)i * DD + blockIdx.x * 128) * NN;
    size_t offB = ((size_t)j * DD + blockIdx.y * 128) * NN;
    const __nv_bfloat16* Ah = g_Yhi + offA;
    const __nv_bfloat16* Al = g_Ylo + offA;
    const __nv_bfloat16* Bh = g_Yhi + offB;
    const __nv_bfloat16* Bl = g_Ylo + offB;
    const int NCH = NN / KC;  // 64 chunks

    int wm = wid & 1, wn = wid >> 1;

    // bf16 m16n8k16 ldmatrix lane maps (8-granule = 16B = 8 bf16 rows of 128B)
    int a_row_off = (lane & 7) + ((lane >> 3) & 1) * 8;  // tile rows
    int a_kh = (lane >> 4) & 1;                          // k granule within ks
    int b_row_off = (lane & 7) + ((lane >> 4) & 1) * 8;
    int b_kh = (lane >> 3) & 1;

    uint32_t arow[4], aph[4];
#pragma unroll
    for (int mt = 0; mt < 4; mt++) {
        int r = wm * 64 + mt * 16 + a_row_off;
        arow[mt] = r * 128; aph[mt] = r & 7;
    }
    uint32_t brow[2], bph[2];
#pragma unroll
    for (int np = 0; np < 2; np++) {
        int r = wn * 32 + np * 16 + b_row_off;
        brow[np] = r * 128; bph[np] = r & 7;
    }

    float c[4][4][4];    // short-chain mma accumulator (reset per chunk)
    float tot[4][4][4];  // unbiased fp32 running total (FADD, RNE)
#pragma unroll
    for (int mt = 0; mt < 4; mt++)
#pragma unroll
        for (int nt = 0; nt < 4; nt++)
#pragma unroll
            for (int v = 0; v < 4; v++) { c[mt][nt][v] = 0.f; tot[mt][nt][v] = 0.f; }

    auto load_stage = [&](int st, int kb) {
        uint32_t s0 = sb + st * STG_BYTES;
        const __nv_bfloat16* srcs[4] = {Ah, Al, Bh, Bl};
#pragma unroll
        for (int arr = 0; arr < 4; arr++) {
            uint32_t base = s0 + arr * SUB;
            const __nv_bfloat16* src = srcs[arr];
#pragma unroll
            for (int t = 0; t < 4; t++) {
                int o = tid + t * 256;
                int r = o >> 3, g = o & 7;     // 128 rows x 8 granules (16B = 8 bf16)
                cp16(base + r * 128 + ((g ^ (r & 7)) * 16), src + (size_t)r * NN + kb + g * 8);
            }
        }
    };

    load_stage(0, 0);
    asm volatile("cp.async.commit_group;");
    load_stage(1, KC);
    asm volatile("cp.async.commit_group;");

    for (int ch = 0; ch < NCH; ch++) {
        asm volatile("cp.async.wait_group %0;" :: "n"(1));
        __syncthreads();

        if (ch + 2 < NCH) load_stage((ch + 2) % NSTG, (ch + 2) * KC);
        asm volatile("cp.async.commit_group;");

        uint32_t s0 = sb + (ch % NSTG) * STG_BYTES;
        uint32_t sAh = s0, sAl = s0 + SUB, sBh = s0 + 2 * SUB, sBl = s0 + 3 * SUB;

#pragma unroll
        for (int ks = 0; ks < 4; ks++) {   // k16 per step, 4 steps = KC 64
            uint32_t ah[4][4], al[4][4];
#pragma unroll
            for (int mt = 0; mt < 4; mt++) {
                uint32_t g = (uint32_t)(ks * 2 + a_kh) ^ aph[mt];
                ldsm4(ah[mt][0], ah[mt][1], ah[mt][2], ah[mt][3], sAh + arow[mt] + g * 16);
                ldsm4(al[mt][0], al[mt][1], al[mt][2], al[mt][3], sAl + arow[mt] + g * 16);
            }
            uint32_t bh[4][2], bl[4][2];
#pragma unroll
            for (int np = 0; np < 2; np++) {
                uint32_t g = (uint32_t)(ks * 2 + b_kh) ^ bph[np];
                ldsm4(bh[np * 2][0], bh[np * 2][1], bh[np * 2 + 1][0], bh[np * 2 + 1][1],
                      sBh + brow[np] + g * 16);
                ldsm4(bl[np * 2][0], bl[np * 2][1], bl[np * 2 + 1][0], bl[np * 2 + 1][1],
                      sBl + brow[np] + g * 16);
            }
            // independent MMA passes (no back-to-back RAW on same accumulator)
#pragma unroll
            for (int mt = 0; mt < 4; mt++)
#pragma unroll
                for (int nt = 0; nt < 4; nt++)
                    mma_bf16(c[mt][nt], ah[mt], bh[nt]);   // hi*hi
#pragma unroll
            for (int mt = 0; mt < 4; mt++)
#pragma unroll
                for (int nt = 0; nt < 4; nt++)
                    mma_bf16(c[mt][nt], ah[mt], bl[nt]);   // hi*lo
#pragma unroll
            for (int mt = 0; mt < 4; mt++)
#pragma unroll
                for (int nt = 0; nt < 4; nt++)
                    mma_bf16(c[mt][nt], al[mt], bh[nt]);   // lo*hi
        }

        // flush 12-mma RZ chain into unbiased fp32 total; reset (bias fix)
#pragma unroll
        for (int mt = 0; mt < 4; mt++)
#pragma unroll
            for (int nt = 0; nt < 4; nt++)
#pragma unroll
                for (int v = 0; v < 4; v++) {
                    tot[mt][nt][v] += c[mt][nt][v];
                    c[mt][nt][v] = 0.f;
                }
    }

    // epilogue: Frobenius square-sum of complete C tile, in double
    double s = 0.0;
#pragma unroll
    for (int mt = 0; mt < 4; mt++)
#pragma unroll
        for (int nt = 0; nt < 4; nt++)
#pragma unroll
            for (int v = 0; v < 4; v++) {
                double f = (double)tot[mt][nt][v];
                s += f * f;
            }
    s *= wgt;
#pragma unroll
    for (int o = 16; o; o >>= 1) s += __shfl_xor_sync(0xffffffffu, s, o);
    __shared__ double red[8];
    if (lane == 0) red[wid] = s;
    __syncthreads();
    if (tid < 8) {
        double v = red[tid];
#pragma unroll
        for (int o = 4; o; o >>= 1) v += __shfl_xor_sync(0xffu, v, o);
        if (tid == 0) atomicAdd(&g_F[p], v);
    }
}

// ---------------------------------------------------------------------------
// Kernel 4: scalar correction sums (double).
// ---------------------------------------------------------------------------
__global__ void k_small() {
    int i = blockIdx.x / 6, j = blockIdx.x % 6;
    const float* qi = g_rq + i * NN;
    const float* dj = g_rd + j * NN;
    const float* di = g_rd + i * NN;
    double aqd = 0.0, add = 0.0, as = 0.0;
    for (int n = threadIdx.x; n < NN; n += 256) {
        double dv = (double)dj[n];
        aqd += (double)qi[n] * dv;
        add += (double)di[n] * dv;
        as += dv;
    }
    int lane = threadIdx.x & 31;
#pragma unroll
    for (int o = 16; o; o >>= 1) {
        aqd += __shfl_xor_sync(0xffffffffu, aqd, o);
        add += __shfl_xor_sync(0xffffffffu, add, o);
        as  += __shfl_xor_sync(0xffffffffu, as, o);
    }
    __shared__ double r0[8], r1[8], r2[8];
    if (lane == 0) { int w = threadIdx.x >> 5; r0[w] = aqd; r1[w] = add; r2[w] = as; }
    __syncthreads();
    if (threadIdx.x == 0) {
        double t0 = 0, t1 = 0, t2 = 0;
#pragma unroll
        for (int w = 0; w < 8; w++) { t0 += r0[w]; t1 += r1[w]; t2 += r2[w]; }
        g_T[i * 6 + j] = t0;
        g_P[i * 6 + j] = t1;
        if (i == j) g_s[i] = t2;
    }
}

// ---------------------------------------------------------------------------
// Kernel 5: finalize.
// ---------------------------------------------------------------------------
__global__ void k_final(float* __restrict__ out) {
    __shared__ double S[36];
    int t = threadIdx.x;
    if (t < 36) {
        int i = t / 6, j = t % 6;
        int a = i < j ? i : j, b = i < j ? j : i;
        int p = a * ML - a * (a + 1) / 2 + b;
        double hs = g_F[p] - g_T[i * 6 + j] - g_T[j * 6 + i]
                  + (1.0 - 2.0 / (double)NN) * g_P[i * 6 + j]
                  + g_s[i] * g_s[j] / ((double)NN * (double)NN);
        S[t] = fabs(hs);
    }
    __syncthreads();
    if (t < 36) {
        int i = t / 6, j = t % 6;
        double v = (i == j) ? 1.0 : S[i * 6 + j] / sqrt(S[i * 6 + i] * S[j * 6 + j] + 1e-6);
        out[t] = (float)v;
    }
    if (t == 0) {
        double l = 0.0;
        for (int i = 0; i < 6; i++)
            for (int j = 0; j < i; j++)
                l += S[i * 6 + j] / sqrt(S[i * 6 + i] * S[j * 6 + j] + 1e-6);
        out[36] = (float)l;
    }
}

// ---------------------------------------------------------------------------
extern "C" void kernel_launch(void* const* d_in, const int* in_sizes, int n_in,
                              void* d_out, int out_size) {
    const float* X = (const float*)d_in[0];
    float* out = (float*)d_out;
    (void)in_sizes; (void)n_in; (void)out_size;

    cudaFuncSetAttribute(k_gemm_mma, cudaFuncAttributeMaxDynamicSharedMemorySize, GEMM_SMEM);
    cudaFuncSetAttribute(k_center_t, cudaFuncAttributeMaxDynamicSharedMemorySize,
                         (2 * 32 * 513 + 512) * 4);

    dim3 g1(ML, DD / 32), b1(32, 8);
    k_mean<<<g1, b1>>>(X);
    k_center_t<<<ML * NN / 32, 256, (2 * 32 * 513 + 512) * 4>>>(X);
    dim3 g3(4, 4, NPAIR);
    k_gemm_mma<<<g3, 256, GEMM_SMEM>>>();
    k_small<<<36, 256>>>();
    k_final<<<1, 64>>>(out);
}